// round 1
// baseline (speedup 1.0000x reference)
#include <cuda_runtime.h>
#include <math.h>
#include <stdint.h>

// Problem sizes (fixed by the dataset)
#define BATCH 4096
#define DIM   1024
#define NROWS 30

// ---------------------------------------------------------------------------
// Scratch (no cudaMalloc allowed): book_emb | change_emb concatenated per row.
// ---------------------------------------------------------------------------
__device__ __align__(16) float g_embs[(size_t)BATCH * 2048];
__device__ __align__(16) float g_vcancel[DIM];
__device__ float g_scancel;

__device__ __forceinline__ uint32_t f2tf32(float f) {
    uint32_t u;
    asm("cvt.rna.tf32.f32 %0, %1;" : "=r"(u) : "f"(f));
    return u;
}

__device__ __forceinline__ float dot4(float4 a, float4 b) {
    return a.x * b.x + a.y * b.y + a.z * b.z + a.w * b.w;
}

#define MMA_TF32(C, A, Bv)                                                     \
    asm volatile(                                                              \
        "mma.sync.aligned.m16n8k8.row.col.f32.tf32.tf32.f32 "                  \
        "{%0,%1,%2,%3}, {%4,%5,%6,%7}, {%8,%9}, {%0,%1,%2,%3};"                \
        : "+f"((C)[0]), "+f"((C)[1]), "+f"((C)[2]), "+f"((C)[3])               \
        : "r"((A)[0]), "r"((A)[1]), "r"((A)[2]), "r"((A)[3]),                  \
          "r"((Bv)[0]), "r"((Bv)[1]))

// ---------------------------------------------------------------------------
// Kernel 1: fold cancel path.  v[k] = sum_i gw[i] * Wc[i,k];
//           g_scancel = sum_i gw[i] * cancel_b[i]
// Grid: 32 blocks x 256 threads. Each block owns 32 k-columns.
// ---------------------------------------------------------------------------
__global__ void matvec_cancel(const float* __restrict__ Wc,
                              const float* __restrict__ cb,
                              const float* __restrict__ gw) {
    __shared__ float red[8][32];
    __shared__ float sred[8];
    const int t = threadIdx.x, w = t >> 5, l = t & 31;
    const int k = blockIdx.x * 32 + l;

    float acc = 0.f;
    for (int i = w; i < DIM; i += 8)
        acc += Wc[(size_t)i * DIM + k] * gw[i];
    red[w][l] = acc;
    __syncthreads();
    if (w == 0) {
        float s = 0.f;
        #pragma unroll
        for (int j = 0; j < 8; j++) s += red[j][l];
        g_vcancel[k] = s;
    }
    if (blockIdx.x == 0) {
        float p = 0.f;
        for (int i = t; i < DIM; i += 256) p += cb[i] * gw[i];
        #pragma unroll
        for (int o = 16; o > 0; o >>= 1) p += __shfl_down_sync(0xffffffffu, p, o);
        if (l == 0) sred[w] = p;
        __syncthreads();
        if (t == 0) {
            float s = 0.f;
            #pragma unroll
            for (int j = 0; j < 8; j++) s += sred[j];
            g_scancel = s;
        }
    }
}

// ---------------------------------------------------------------------------
// Kernel 2: TF32 GEMM.  C[4096, 2048] = X[4096,1024] @ [book_W; change_W]^T
//           + bias, written to g_embs.
// Block tile 128x128x32, 256 threads (8 warps of 64x32), mma.m16n8k8.
// Shared layout [row][k] with stride 36 floats -> conflict-free frag loads.
// ---------------------------------------------------------------------------
__global__ void __launch_bounds__(256)
gemm_tf32(const float* __restrict__ X,
          const float* __restrict__ Wb, const float* __restrict__ Wch,
          const float* __restrict__ bb, const float* __restrict__ bch) {
    __shared__ uint32_t As[128][36];
    __shared__ uint32_t Bs[128][36];

    const int t = threadIdx.x;
    const int warp = t >> 5, lane = t & 31;
    const int wm = warp >> 2, wn = warp & 3;   // 2 x 4 warp grid
    const int g = lane >> 2, tg = lane & 3;

    const int m0 = blockIdx.y * 128;
    const int n0 = blockIdx.x * 128;

    const float* Wsel;
    const float* bsel;
    if (n0 < 1024) { Wsel = Wb + (size_t)n0 * DIM;            bsel = bb + n0; }
    else           { Wsel = Wch + (size_t)(n0 - 1024) * DIM;  bsel = bch + (n0 - 1024); }

    float acc[4][4][4];
    #pragma unroll
    for (int mt = 0; mt < 4; mt++)
        #pragma unroll
        for (int nt = 0; nt < 4; nt++)
            #pragma unroll
            for (int j = 0; j < 4; j++) acc[mt][nt][j] = 0.f;

    float4 pa[4], pb[4];
    // prologue: load stage kb=0 into registers
    #pragma unroll
    for (int i = 0; i < 4; i++) {
        const int lin = t + 256 * i;
        const int m = lin >> 3, kq = lin & 7;
        pa[i] = *(const float4*)(X + (size_t)(m0 + m) * DIM + kq * 4);
        pb[i] = *(const float4*)(Wsel + (size_t)m * DIM + kq * 4);
    }

    for (int kb = 0; kb < DIM; kb += 32) {
        // convert + store current stage to shared
        #pragma unroll
        for (int i = 0; i < 4; i++) {
            const int lin = t + 256 * i;
            const int m = lin >> 3, kq = lin & 7;
            uint4 ua = make_uint4(f2tf32(pa[i].x), f2tf32(pa[i].y),
                                  f2tf32(pa[i].z), f2tf32(pa[i].w));
            *(uint4*)&As[m][kq * 4] = ua;
            uint4 ub = make_uint4(f2tf32(pb[i].x), f2tf32(pb[i].y),
                                  f2tf32(pb[i].z), f2tf32(pb[i].w));
            *(uint4*)&Bs[m][kq * 4] = ub;
        }
        __syncthreads();

        // prefetch next stage
        if (kb + 32 < DIM) {
            #pragma unroll
            for (int i = 0; i < 4; i++) {
                const int lin = t + 256 * i;
                const int m = lin >> 3, kq = lin & 7;
                pa[i] = *(const float4*)(X + (size_t)(m0 + m) * DIM + kb + 32 + kq * 4);
                pb[i] = *(const float4*)(Wsel + (size_t)m * DIM + kb + 32 + kq * 4);
            }
        }

        // compute 4 x k8 steps
        #pragma unroll
        for (int ks = 0; ks < 4; ks++) {
            const int k8 = ks * 8;
            uint32_t af[4][4], bf[4][2];
            #pragma unroll
            for (int mt = 0; mt < 4; mt++) {
                const int ra = wm * 64 + mt * 16 + g;
                af[mt][0] = As[ra][k8 + tg];
                af[mt][1] = As[ra + 8][k8 + tg];
                af[mt][2] = As[ra][k8 + tg + 4];
                af[mt][3] = As[ra + 8][k8 + tg + 4];
            }
            #pragma unroll
            for (int nt = 0; nt < 4; nt++) {
                const int cn = wn * 32 + nt * 8 + g;
                bf[nt][0] = Bs[cn][k8 + tg];
                bf[nt][1] = Bs[cn][k8 + tg + 4];
            }
            #pragma unroll
            for (int mt = 0; mt < 4; mt++)
                #pragma unroll
                for (int nt = 0; nt < 4; nt++)
                    MMA_TF32(acc[mt][nt], af[mt], bf[nt]);
        }
        __syncthreads();
    }

    // epilogue: add bias, store to scratch
    #pragma unroll
    for (int mt = 0; mt < 4; mt++) {
        #pragma unroll
        for (int nt = 0; nt < 4; nt++) {
            const int row = m0 + wm * 64 + mt * 16 + g;
            const int col = wn * 32 + nt * 8 + 2 * tg;
            const float b0 = bsel[col], b1 = bsel[col + 1];
            float2 v01 = make_float2(acc[mt][nt][0] + b0, acc[mt][nt][1] + b1);
            float2 v23 = make_float2(acc[mt][nt][2] + b0, acc[mt][nt][3] + b1);
            *(float2*)&g_embs[(size_t)row * 2048 + n0 + col] = v01;
            *(float2*)&g_embs[(size_t)(row + 8) * 2048 + n0 + col] = v23;
        }
    }
}

// ---------------------------------------------------------------------------
// Kernel 3: fused epilogue. One CTA (256 thr) per batch row.
//   phase 1: 9 cooperative 1024-dots (no-flight x2, gates, goal logits)
//   phase 2: 30 table-row dual dots (DRAM-bound: 120KB/row streamed)
//   phase 3: softmaxes + 63-way mix
// ---------------------------------------------------------------------------
__global__ void __launch_bounds__(256)
epilogue_kernel(const float* __restrict__ X, const float* __restrict__ table,
                const float* __restrict__ nf, const float* __restrict__ res,
                const float* __restrict__ goalW, const float* __restrict__ goalb,
                const float* __restrict__ chgW, const float* __restrict__ chgb,
                const float* __restrict__ ccgW, const float* __restrict__ ccgb,
                float* __restrict__ out) {
    const int b = blockIdx.x;
    const int t = threadIdx.x, w = t >> 5, l = t & 31;

    __shared__ float red[8][9];
    __shared__ float sdots[9];
    __shared__ float slb[31], slc[31], spb[31], spc[31];
    __shared__ float sc[4];

    const float* be  = g_embs + (size_t)b * 2048;
    const float* ce  = be + 1024;
    const float* xb  = X   + (size_t)b * DIM;
    const float* nfb = nf  + (size_t)b * DIM;
    const float* rb  = res + (size_t)b * DIM;

    // ---- phase 1: nine 1024-length dot products ----
    float p[9];
    {
        const int i0 = t * 4;
        float4 xv = *(const float4*)(xb + i0);
        float4 nv = *(const float4*)(nfb + i0);
        float4 rv = *(const float4*)(rb + i0);
        float4 bv = *(const float4*)(be + i0);
        float4 cv = *(const float4*)(ce + i0);
        float4 g0 = *(const float4*)(goalW + i0);
        float4 g1 = *(const float4*)(goalW + 1024 + i0);
        float4 g2 = *(const float4*)(goalW + 2048 + i0);
        float4 cl = *(const float4*)(chgW + i0);
        float4 ch = *(const float4*)(chgW + 1024 + i0);
        float4 kh = *(const float4*)(ccgW + 1024 + i0);
        float4 vc = *(const float4*)(g_vcancel + i0);
        p[0] = dot4(bv, nv);   // book . no_flight
        p[1] = dot4(cv, nv);   // change . no_flight
        p[2] = dot4(cv, cl);   // change_emb . chgW_lo
        p[3] = dot4(rv, ch);   // res . chgW_hi
        p[4] = dot4(xv, vc);   // X . v_cancel
        p[5] = dot4(rv, kh);   // res . ccgW_hi
        p[6] = dot4(xv, g0);   // goal logits
        p[7] = dot4(xv, g1);
        p[8] = dot4(xv, g2);
    }
    #pragma unroll
    for (int j = 0; j < 9; j++) {
        #pragma unroll
        for (int o = 16; o > 0; o >>= 1)
            p[j] += __shfl_down_sync(0xffffffffu, p[j], o);
    }
    if (l == 0) {
        #pragma unroll
        for (int j = 0; j < 9; j++) red[w][j] = p[j];
    }
    __syncthreads();
    if (t < 9) {
        float s = 0.f;
        #pragma unroll
        for (int ww = 0; ww < 8; ww++) s += red[ww][t];
        sdots[t] = s;
    }

    // ---- phase 2: table logits (dual dot per row, register-resident embs) ----
    {
        float4 eb[8], ec[8];
        const float4* be4 = (const float4*)be;
        const float4* ce4 = (const float4*)ce;
        #pragma unroll
        for (int j = 0; j < 8; j++) {
            eb[j] = be4[j * 32 + l];
            ec[j] = ce4[j * 32 + l];
        }
        for (int r = w; r < NROWS; r += 8) {
            const float4* t4 = (const float4*)(table + ((size_t)b * NROWS + r) * DIM);
            float ab = 0.f, ac = 0.f;
            #pragma unroll
            for (int j = 0; j < 8; j++) {
                float4 tv = t4[j * 32 + l];
                ab += dot4(tv, eb[j]);
                ac += dot4(tv, ec[j]);
            }
            #pragma unroll
            for (int o = 16; o > 0; o >>= 1) {
                ab += __shfl_down_sync(0xffffffffu, ab, o);
                ac += __shfl_down_sync(0xffffffffu, ac, o);
            }
            if (l == 0) {
                slb[r + 1] = ab * 0.03125f;   // 1/sqrt(1024)
                slc[r + 1] = ac * 0.03125f;
            }
        }
    }
    __syncthreads();

    // ---- phase 3a: scalars ----
    if (t == 0) {
        slb[0] = sdots[0] * 0.03125f;
        slc[0] = sdots[1] * 0.03125f;
        float l0 = sdots[6] + goalb[0];
        float l1 = sdots[7] + goalb[1];
        float l2 = sdots[8] + goalb[2];
        float mx = fmaxf(l0, fmaxf(l1, l2));
        float e0 = expf(l0 - mx), e1 = expf(l1 - mx), e2 = expf(l2 - mx);
        float inv = 1.f / (e0 + e1 + e2);
        float bg = e0 * inv, chg = e1 * inv, cang = e2 * inv;
        float change_prob = 1.f / (1.f + expf(-(sdots[2] + sdots[3] + chgb[0])));
        float cancel_prob = 1.f / (1.f + expf(-(sdots[4] + sdots[5] + g_scancel + ccgb[0])));
        sc[0] = bg;                       // book goal
        sc[1] = chg * change_prob;        // effective change weight
        sc[2] = cang * cancel_prob;       // col_cancel
        sc[3] = cang * (1.f - cancel_prob) + chg * (1.f - change_prob);  // col_no_res
    }
    __syncthreads();

    // ---- phase 3b: two 31-way softmaxes (warp 0: book, warp 1: change) ----
    if (w < 2) {
        float* sl = w ? slc : slb;
        float* sp = w ? spc : spb;
        float v = (l < 31) ? sl[l] : -1e30f;
        float mx = v;
        #pragma unroll
        for (int o = 16; o > 0; o >>= 1)
            mx = fmaxf(mx, __shfl_xor_sync(0xffffffffu, mx, o));
        float e = (l < 31) ? expf(v - mx) : 0.f;
        float s = e;
        #pragma unroll
        for (int o = 16; o > 0; o >>= 1)
            s += __shfl_xor_sync(0xffffffffu, s, o);
        if (l < 31) sp[l] = e / s;
    }
    __syncthreads();

    // ---- phase 3c: final 63 outputs ----
    if (t < 63) {
        float o;
        if (t == 0)       o = sc[0] * spb[0] + sc[1] * spc[0];
        else if (t == 1)  o = sc[2];
        else if (t == 2)  o = sc[3];
        else if (t < 33)  o = sc[0] * spb[t - 2];
        else              o = sc[1] * spc[t - 32];
        out[(size_t)b * 63 + t] = o;
    }
}

// ---------------------------------------------------------------------------
extern "C" void kernel_launch(void* const* d_in, const int* in_sizes, int n_in,
                              void* d_out, int out_size) {
    const float* X     = (const float*)d_in[0];   // constraint_embs (B, D)
    const float* table = (const float*)d_in[1];   // table_embs (B, R, D)
    const float* nf    = (const float*)d_in[2];   // no_flight_emb (B, D)
    const float* res   = (const float*)d_in[3];   // res_emb (B, D)
    const float* goalW = (const float*)d_in[4];   // (3, D)
    const float* goalb = (const float*)d_in[5];   // (3,)
    const float* bookW = (const float*)d_in[6];   // (D, D)
    const float* bookb = (const float*)d_in[7];   // (D,)
    const float* chW   = (const float*)d_in[8];   // (D, D)
    const float* chb   = (const float*)d_in[9];   // (D,)
    const float* ccW   = (const float*)d_in[10];  // (D, D)
    const float* ccb   = (const float*)d_in[11];  // (D,)
    const float* chgW  = (const float*)d_in[12];  // (1, 2D)
    const float* chgb  = (const float*)d_in[13];  // (1,)
    const float* ccgW  = (const float*)d_in[14];  // (1, 2D)
    const float* ccgb  = (const float*)d_in[15];  // (1,)
    float* out = (float*)d_out;

    matvec_cancel<<<32, 256>>>(ccW, ccb, ccgW);

    dim3 ggrid(2048 / 128, BATCH / 128);
    gemm_tf32<<<ggrid, 256>>>(X, bookW, chW, bookb, chb);

    epilogue_kernel<<<BATCH, 256>>>(X, table, nf, res, goalW, goalb,
                                    chgW, chgb, ccgW, ccgb, out);
}

// round 2
// speedup vs baseline: 1.5232x; 1.5232x over previous
#include <cuda_runtime.h>
#include <cuda_bf16.h>
#include <math.h>
#include <stdint.h>

#define BATCH 4096
#define DIM   1024
#define NROWS 30

// ---------------------------------------------------------------------------
// Scratch (no cudaMalloc allowed)
// ---------------------------------------------------------------------------
__device__ __align__(16) float g_embs[(size_t)BATCH * 2048];      // book|change fp32
__device__ __align__(16) __nv_bfloat16 g_xbf[(size_t)BATCH * DIM];  // X in bf16
__device__ __align__(16) __nv_bfloat16 g_wbf[(size_t)2048 * DIM];   // [book_W; change_W] bf16
__device__ __align__(16) float g_vcancel[DIM];
__device__ float g_scancel;

__device__ __forceinline__ float dot4(float4 a, float4 b) {
    return a.x * b.x + a.y * b.y + a.z * b.z + a.w * b.w;
}

__device__ __forceinline__ void cp16(uint32_t dst, const void* src) {
    asm volatile("cp.async.cg.shared.global [%0], [%1], 16;\n" :: "r"(dst), "l"(src));
}
__device__ __forceinline__ void cp_commit() {
    asm volatile("cp.async.commit_group;\n");
}
template <int N>
__device__ __forceinline__ void cp_wait() {
    asm volatile("cp.async.wait_group %0;\n" :: "n"(N));
}

__device__ __forceinline__ void ldmx4(uint32_t* r, uint32_t addr) {
    asm volatile("ldmatrix.sync.aligned.m8n8.x4.shared.b16 {%0,%1,%2,%3}, [%4];"
                 : "=r"(r[0]), "=r"(r[1]), "=r"(r[2]), "=r"(r[3]) : "r"(addr));
}

#define MMA_BF16(C, A, B0, B1)                                                 \
    asm volatile(                                                              \
        "mma.sync.aligned.m16n8k16.row.col.f32.bf16.bf16.f32 "                 \
        "{%0,%1,%2,%3}, {%4,%5,%6,%7}, {%8,%9}, {%0,%1,%2,%3};"                \
        : "+f"((C)[0]), "+f"((C)[1]), "+f"((C)[2]), "+f"((C)[3])               \
        : "r"((A)[0]), "r"((A)[1]), "r"((A)[2]), "r"((A)[3]),                  \
          "r"(B0), "r"(B1))

// ---------------------------------------------------------------------------
// Kernel 0: zero g_vcancel + compute g_scancel = gw . cancel_b.  1 block.
// ---------------------------------------------------------------------------
__global__ void zero_and_scancel(const float* __restrict__ cb,
                                 const float* __restrict__ gw) {
    __shared__ float red[8];
    const int t = threadIdx.x, w = t >> 5, l = t & 31;
    ((float4*)g_vcancel)[t] = make_float4(0.f, 0.f, 0.f, 0.f);
    float4 c = ((const float4*)cb)[t];
    float4 g = ((const float4*)gw)[t];
    float p = dot4(c, g);
    #pragma unroll
    for (int o = 16; o > 0; o >>= 1) p += __shfl_down_sync(0xffffffffu, p, o);
    if (l == 0) red[w] = p;
    __syncthreads();
    if (t == 0) {
        float s = 0.f;
        #pragma unroll
        for (int j = 0; j < 8; j++) s += red[j];
        g_scancel = s;
    }
}

// ---------------------------------------------------------------------------
// Kernel 1: v[k] += sum over 32 rows of gw[i]*Wc[i,k].  grid (4, 32) x 256.
// ---------------------------------------------------------------------------
__global__ void matvec_cancel(const float* __restrict__ Wc,
                              const float* __restrict__ gw) {
    const int k  = blockIdx.x * 256 + threadIdx.x;
    const int i0 = blockIdx.y * 32;
    float acc = 0.f;
    #pragma unroll
    for (int j = 0; j < 32; j++)
        acc += Wc[(size_t)(i0 + j) * DIM + k] * __ldg(gw + i0 + j);
    atomicAdd(&g_vcancel[k], acc);
}

// ---------------------------------------------------------------------------
// Kernel 2: fp32 -> bf16 conversion of X, book_W, change_W.
// grid 3072 x 256, each thread converts 8 floats.
// ---------------------------------------------------------------------------
__global__ void conv_bf16(const float* __restrict__ X,
                          const float* __restrict__ Wb,
                          const float* __restrict__ Wc) {
    const int b = blockIdx.x, t = threadIdx.x;
    const float* src;
    __nv_bfloat16* dst;
    size_t off;
    if (b < 2048)      { src = X;  dst = g_xbf;            off = (size_t)b * 2048 + t * 8; }
    else if (b < 2560) { src = Wb; dst = g_wbf;            off = (size_t)(b - 2048) * 2048 + t * 8; }
    else               { src = Wc; dst = g_wbf + (1u<<20); off = (size_t)(b - 2560) * 2048 + t * 8; }
    float4 a0 = *(const float4*)(src + off);
    float4 a1 = *(const float4*)(src + off + 4);
    __nv_bfloat162 h0 = __floats2bfloat162_rn(a0.x, a0.y);
    __nv_bfloat162 h1 = __floats2bfloat162_rn(a0.z, a0.w);
    __nv_bfloat162 h2 = __floats2bfloat162_rn(a1.x, a1.y);
    __nv_bfloat162 h3 = __floats2bfloat162_rn(a1.z, a1.w);
    uint4 o;
    o.x = *(uint32_t*)&h0; o.y = *(uint32_t*)&h1;
    o.z = *(uint32_t*)&h2; o.w = *(uint32_t*)&h3;
    *(uint4*)(dst + off) = o;
}

// ---------------------------------------------------------------------------
// Kernel 3: bf16 GEMM.  C[4096,2048] = Xbf @ Wbf^T + bias -> g_embs (fp32).
// 128x128x64 stages, cp.async double buffer, mma.m16n8k16, XOR-swizzled
// ldmatrix loads (conflict-free). 256 threads = 8 warps of 64x32.
// Dynamic smem: As[2][128][64]bf16 (32KB) + Bs same = 64KB.
// ---------------------------------------------------------------------------
__global__ void __launch_bounds__(256)
gemm_bf16(const float* __restrict__ bb, const float* __restrict__ bch) {
    extern __shared__ char smem[];
    const uint32_t baseA = (uint32_t)__cvta_generic_to_shared(smem);
    const uint32_t baseB = baseA + 32768;

    const int t = threadIdx.x;
    const int warp = t >> 5, lane = t & 31;
    const int wm = warp >> 2, wn = warp & 3;
    const int g = lane >> 2, tg = lane & 3;
    const int q = lane >> 3, r8 = lane & 7;
    const int qm = (q & 1) * 8 + r8;     // row offset within 16-row ldmatrix tile
    const int qk = (q >> 1) * 8;         // k-half offset

    const int m0 = blockIdx.y * 128;
    const int n0 = blockIdx.x * 128;

    float acc[4][4][4];
    #pragma unroll
    for (int mt = 0; mt < 4; mt++)
        #pragma unroll
        for (int nt = 0; nt < 4; nt++)
            #pragma unroll
            for (int j = 0; j < 4; j++) acc[mt][nt][j] = 0.f;

    // precompute per-thread load coords: 4 chunks of 16B per matrix per stage
    int lm[4], lc[4];
    #pragma unroll
    for (int i = 0; i < 4; i++) {
        int chunk = t + 256 * i;
        lm[i] = chunk >> 3;
        lc[i] = chunk & 7;
    }

    auto issue = [&](int s) {
        const int buf = s & 1;
        const int kb = s * 64;
        const uint32_t bo = buf * 16384;
        #pragma unroll
        for (int i = 0; i < 4; i++) {
            const int m = lm[i], c = lc[i];
            const int pc = c ^ (m & 7);
            cp16(baseA + bo + m * 128 + pc * 16,
                 g_xbf + (size_t)(m0 + m) * DIM + kb + c * 8);
            cp16(baseB + bo + m * 128 + pc * 16,
                 g_wbf + (size_t)(n0 + m) * DIM + kb + c * 8);
        }
        cp_commit();
    };

    issue(0);

    for (int s = 0; s < 16; s++) {
        __syncthreads();                 // protect buffer being re-issued
        if (s < 15) { issue(s + 1); cp_wait<1>(); }
        else        { cp_wait<0>(); }
        __syncthreads();

        const uint32_t bo = (s & 1) * 16384;
        #pragma unroll
        for (int ks = 0; ks < 4; ks++) {
            const int kk = ks * 16;
            uint32_t af[4][4];
            #pragma unroll
            for (int mt = 0; mt < 4; mt++) {
                const int m = wm * 64 + mt * 16 + qm;
                const int kc = kk + qk;
                ldmx4(af[mt], baseA + bo + m * 128 + (((kc >> 3) ^ (m & 7)) * 16));
            }
            uint32_t b0[4], b1[4];
            #pragma unroll
            for (int ntp = 0; ntp < 2; ntp++) {
                const int n = wn * 32 + ntp * 16 + qm;
                const int kc = kk + qk;
                uint32_t r[4];
                ldmx4(r, baseB + bo + n * 128 + (((kc >> 3) ^ (n & 7)) * 16));
                b0[2 * ntp] = r[0]; b0[2 * ntp + 1] = r[1];
                b1[2 * ntp] = r[2]; b1[2 * ntp + 1] = r[3];
            }
            #pragma unroll
            for (int mt = 0; mt < 4; mt++)
                #pragma unroll
                for (int nt = 0; nt < 4; nt++)
                    MMA_BF16(acc[mt][nt], af[mt], b0[nt], b1[nt]);
        }
    }

    const float* bsel = (n0 < 1024) ? (bb + n0) : (bch + (n0 - 1024));
    #pragma unroll
    for (int mt = 0; mt < 4; mt++) {
        #pragma unroll
        for (int nt = 0; nt < 4; nt++) {
            const int row = m0 + wm * 64 + mt * 16 + g;
            const int col = wn * 32 + nt * 8 + 2 * tg;
            const float c0 = bsel[col], c1 = bsel[col + 1];
            float2 v01 = make_float2(acc[mt][nt][0] + c0, acc[mt][nt][1] + c1);
            float2 v23 = make_float2(acc[mt][nt][2] + c0, acc[mt][nt][3] + c1);
            *(float2*)&g_embs[(size_t)row * 2048 + n0 + col] = v01;
            *(float2*)&g_embs[(size_t)(row + 8) * 2048 + n0 + col] = v23;
        }
    }
}

// ---------------------------------------------------------------------------
// Kernel 4: fused epilogue. One CTA (256 thr) per batch row.
// ---------------------------------------------------------------------------
__global__ void __launch_bounds__(256)
epilogue_kernel(const float* __restrict__ X, const float* __restrict__ table,
                const float* __restrict__ nf, const float* __restrict__ res,
                const float* __restrict__ goalW, const float* __restrict__ goalb,
                const float* __restrict__ chgW, const float* __restrict__ chgb,
                const float* __restrict__ ccgW, const float* __restrict__ ccgb,
                float* __restrict__ out) {
    const int b = blockIdx.x;
    const int t = threadIdx.x, w = t >> 5, l = t & 31;

    __shared__ float red[8][9];
    __shared__ float sdots[9];
    __shared__ float slb[31], slc[31], spb[31], spc[31];
    __shared__ float sc[4];

    const float* be  = g_embs + (size_t)b * 2048;
    const float* ce  = be + 1024;
    const float* xb  = X   + (size_t)b * DIM;
    const float* nfb = nf  + (size_t)b * DIM;
    const float* rb  = res + (size_t)b * DIM;

    // ---- phase 1: nine 1024-length dot products ----
    float p[9];
    {
        const int i0 = t * 4;
        float4 xv = *(const float4*)(xb + i0);
        float4 nv = *(const float4*)(nfb + i0);
        float4 rv = *(const float4*)(rb + i0);
        float4 bv = *(const float4*)(be + i0);
        float4 cv = *(const float4*)(ce + i0);
        float4 g0 = *(const float4*)(goalW + i0);
        float4 g1 = *(const float4*)(goalW + 1024 + i0);
        float4 g2 = *(const float4*)(goalW + 2048 + i0);
        float4 cl = *(const float4*)(chgW + i0);
        float4 ch = *(const float4*)(chgW + 1024 + i0);
        float4 kh = *(const float4*)(ccgW + 1024 + i0);
        float4 vc = *(const float4*)(g_vcancel + i0);
        p[0] = dot4(bv, nv);
        p[1] = dot4(cv, nv);
        p[2] = dot4(cv, cl);
        p[3] = dot4(rv, ch);
        p[4] = dot4(xv, vc);
        p[5] = dot4(rv, kh);
        p[6] = dot4(xv, g0);
        p[7] = dot4(xv, g1);
        p[8] = dot4(xv, g2);
    }
    #pragma unroll
    for (int j = 0; j < 9; j++) {
        #pragma unroll
        for (int o = 16; o > 0; o >>= 1)
            p[j] += __shfl_down_sync(0xffffffffu, p[j], o);
    }
    if (l == 0) {
        #pragma unroll
        for (int j = 0; j < 9; j++) red[w][j] = p[j];
    }
    __syncthreads();
    if (t < 9) {
        float s = 0.f;
        #pragma unroll
        for (int ww = 0; ww < 8; ww++) s += red[ww][t];
        sdots[t] = s;
    }

    // ---- phase 2: table logits ----
    {
        float4 eb[8], ec[8];
        const float4* be4 = (const float4*)be;
        const float4* ce4 = (const float4*)ce;
        #pragma unroll
        for (int j = 0; j < 8; j++) {
            eb[j] = be4[j * 32 + l];
            ec[j] = ce4[j * 32 + l];
        }
        for (int r = w; r < NROWS; r += 8) {
            const float4* t4 = (const float4*)(table + ((size_t)b * NROWS + r) * DIM);
            float ab = 0.f, ac = 0.f;
            #pragma unroll
            for (int j = 0; j < 8; j++) {
                float4 tv = t4[j * 32 + l];
                ab += dot4(tv, eb[j]);
                ac += dot4(tv, ec[j]);
            }
            #pragma unroll
            for (int o = 16; o > 0; o >>= 1) {
                ab += __shfl_down_sync(0xffffffffu, ab, o);
                ac += __shfl_down_sync(0xffffffffu, ac, o);
            }
            if (l == 0) {
                slb[r + 1] = ab * 0.03125f;
                slc[r + 1] = ac * 0.03125f;
            }
        }
    }
    __syncthreads();

    // ---- phase 3a: scalars ----
    if (t == 0) {
        slb[0] = sdots[0] * 0.03125f;
        slc[0] = sdots[1] * 0.03125f;
        float l0 = sdots[6] + goalb[0];
        float l1 = sdots[7] + goalb[1];
        float l2 = sdots[8] + goalb[2];
        float mx = fmaxf(l0, fmaxf(l1, l2));
        float e0 = expf(l0 - mx), e1 = expf(l1 - mx), e2 = expf(l2 - mx);
        float inv = 1.f / (e0 + e1 + e2);
        float bg = e0 * inv, chg = e1 * inv, cang = e2 * inv;
        float change_prob = 1.f / (1.f + expf(-(sdots[2] + sdots[3] + chgb[0])));
        float cancel_prob = 1.f / (1.f + expf(-(sdots[4] + sdots[5] + g_scancel + ccgb[0])));
        sc[0] = bg;
        sc[1] = chg * change_prob;
        sc[2] = cang * cancel_prob;
        sc[3] = cang * (1.f - cancel_prob) + chg * (1.f - change_prob);
    }
    __syncthreads();

    // ---- phase 3b: two 31-way softmaxes ----
    if (w < 2) {
        float* sl = w ? slc : slb;
        float* sp = w ? spc : spb;
        float v = (l < 31) ? sl[l] : -1e30f;
        float mx = v;
        #pragma unroll
        for (int o = 16; o > 0; o >>= 1)
            mx = fmaxf(mx, __shfl_xor_sync(0xffffffffu, mx, o));
        float e = (l < 31) ? expf(v - mx) : 0.f;
        float s = e;
        #pragma unroll
        for (int o = 16; o > 0; o >>= 1)
            s += __shfl_xor_sync(0xffffffffu, s, o);
        if (l < 31) sp[l] = e / s;
    }
    __syncthreads();

    // ---- phase 3c: final 63 outputs ----
    if (t < 63) {
        float o;
        if (t == 0)       o = sc[0] * spb[0] + sc[1] * spc[0];
        else if (t == 1)  o = sc[2];
        else if (t == 2)  o = sc[3];
        else if (t < 33)  o = sc[0] * spb[t - 2];
        else              o = sc[1] * spc[t - 32];
        out[(size_t)b * 63 + t] = o;
    }
}

// ---------------------------------------------------------------------------
extern "C" void kernel_launch(void* const* d_in, const int* in_sizes, int n_in,
                              void* d_out, int out_size) {
    const float* X     = (const float*)d_in[0];
    const float* table = (const float*)d_in[1];
    const float* nf    = (const float*)d_in[2];
    const float* res   = (const float*)d_in[3];
    const float* goalW = (const float*)d_in[4];
    const float* goalb = (const float*)d_in[5];
    const float* bookW = (const float*)d_in[6];
    const float* bookb = (const float*)d_in[7];
    const float* chW   = (const float*)d_in[8];
    const float* chb   = (const float*)d_in[9];
    const float* ccW   = (const float*)d_in[10];
    const float* ccb   = (const float*)d_in[11];
    const float* chgW  = (const float*)d_in[12];
    const float* chgb  = (const float*)d_in[13];
    const float* ccgW  = (const float*)d_in[14];
    const float* ccgb  = (const float*)d_in[15];
    float* out = (float*)d_out;

    static bool attr_set = false;
    if (!attr_set) {
        cudaFuncSetAttribute(gemm_bf16,
                             cudaFuncAttributeMaxDynamicSharedMemorySize, 65536);
        attr_set = true;
    }

    zero_and_scancel<<<1, 256>>>(ccb, ccgW);
    matvec_cancel<<<dim3(4, 32), 256>>>(ccW, ccgW);
    conv_bf16<<<3072, 256>>>(X, bookW, chW);

    dim3 ggrid(2048 / 128, BATCH / 128);
    gemm_bf16<<<ggrid, 256, 65536>>>(bookb, chb);

    epilogue_kernel<<<BATCH, 256>>>(X, table, nf, res, goalW, goalb,
                                    chgW, chgb, ccgW, ccgb, out);
}